// round 14
// baseline (speedup 1.0000x reference)
#include <cuda_runtime.h>
#include <math.h>

// ChamferLoss: B=8, N=M=4096, D=3 — snake-grid sort + block-per-super-cell staged NN.

#define BATCH    8
#define NPTS     4096
#define NCLOUD   16
#define GRID     32
#define NCELL    (GRID * GRID)
#define XMIN     (-3.2f)
#define CELLW    0.2f
#define INV_CELLW 5.0f
#define SUP      16                     // 16x16 super-cells (2x2 cells each)
#define NSUP     (SUP * SUP)            // 256
#define S_THREADS 128
#define CAND_MAX 1024                   // 16 KB float4 buffer
#define NCOMBO   16
#define NBLOCKS  (NCOMBO * NSUP)        // 4096

__device__ float4 g_sorted[NCLOUD][NPTS];        // (x,y,z,|p|^2), snake-cell-sorted
__device__ int    g_cellstart[NCLOUD][NCELL + 1];
__device__ double g_sum  = 0.0;
__device__ unsigned int g_tick = 0;

static __device__ __forceinline__ int clampg(int v) { return min(max(v, 0), GRID - 1); }
static __device__ __forceinline__ int cell_of(float x, float y) {
    int cx = clampg((int)((x - XMIN) * INV_CELLW));
    int cy = clampg((int)((y - XMIN) * INV_CELLW));
    int cxs = (cy & 1) ? (GRID - 1 - cx) : cx;   // snake
    return (cy << 5) | cxs;
}

// ---------------- Kernel 1: snake-cell counting sort, one block per cloud ----------------
__global__ __launch_bounds__(512) void sort_kernel(
    const float* __restrict__ pred,
    const float* __restrict__ targ)
{
    __shared__ int cnt[NCELL];
    __shared__ int ofs[NCELL];
    __shared__ int wtot[16];

    const int c = blockIdx.x;
    const int b = c >> 1;
    const float* __restrict__ src = ((c & 1) ? targ : pred) + (size_t)b * NPTS * 3;
    const int tid = threadIdx.x;

    for (int k = tid; k < NCELL; k += 512) cnt[k] = 0;
    __syncthreads();
    #pragma unroll
    for (int i = tid; i < NPTS; i += 512)
        atomicAdd(&cnt[cell_of(src[3 * i], src[3 * i + 1])], 1);
    __syncthreads();

    {   // exclusive prefix over 1024 cells
        const int base = tid * 2;
        int c0 = cnt[base], c1 = cnt[base + 1];
        int tot = c0 + c1;
        int inc = tot;
        #pragma unroll
        for (int o = 1; o < 32; o <<= 1) {
            int n = __shfl_up_sync(0xFFFFFFFFu, inc, o);
            if ((tid & 31) >= o) inc += n;
        }
        if ((tid & 31) == 31) wtot[tid >> 5] = inc;
        __syncthreads();
        if (tid == 0) {
            int r = 0;
            #pragma unroll
            for (int w = 0; w < 16; w++) { int t = wtot[w]; wtot[w] = r; r += t; }
        }
        __syncthreads();
        int off = (inc - tot) + wtot[tid >> 5];
        ofs[base] = off;            ofs[base + 1] = off + c0;
        g_cellstart[c][base] = off; g_cellstart[c][base + 1] = off + c0;
        if (tid == 511) g_cellstart[c][NCELL] = off + tot;
    }
    __syncthreads();

    #pragma unroll
    for (int i = tid; i < NPTS; i += 512) {
        float x = src[3 * i], y = src[3 * i + 1], z = src[3 * i + 2];
        float w = fmaf(x, x, fmaf(y, y, z * z));
        int pos = atomicAdd(&ofs[cell_of(x, y)], 1);
        g_sorted[c][pos] = make_float4(x, y, z, w);
    }
}

// ---------------- Kernel 2: one block per (combo, super-cell) ----------------
__global__ __launch_bounds__(S_THREADS) void search_kernel(float* __restrict__ out)
{
    __shared__ float4 cand[CAND_MAX];          // 16 KB
    __shared__ float warpsums[S_THREADS / 32];
    __shared__ unsigned int s_done;

    const int tid  = threadIdx.x;
    const int lane = tid & 31;
    const int wid  = tid >> 5;

    const int combo = blockIdx.x >> 8;         // /NSUP
    const int sup   = blockIdx.x & (NSUP - 1);
    const int Sy = sup >> 4, Sx = sup & 15;
    const int b   = combo >> 1;
    const int dir = combo & 1;
    const int cs  = b * 2 + dir;
    const int ct  = b * 2 + (dir ^ 1);
    const int* __restrict__ cstT = g_cellstart[ct];
    const int* __restrict__ cstS = g_cellstart[cs];
    const float4* __restrict__ tgtg = g_sorted[ct];

    // Source runs: super covers cells rows {2Sy, 2Sy+1} x cols {2Sx, 2Sx+1}
    const int scx0 = Sx * 2, scx1 = Sx * 2 + 1;
    int a0, a1, b0r, b1r;
    {
        int ry = Sy * 2;
        int slo = (ry & 1) ? (GRID - 1 - scx1) : scx0;
        int shi = (ry & 1) ? (GRID - 1 - scx0) : scx1;
        a0 = cstS[(ry << 5) + slo]; a1 = cstS[(ry << 5) + shi + 1];
    }
    {
        int ry = Sy * 2 + 1;
        int slo = (ry & 1) ? (GRID - 1 - scx1) : scx0;
        int shi = (ry & 1) ? (GRID - 1 - scx0) : scx1;
        b0r = cstS[(ry << 5) + slo]; b1r = cstS[(ry << 5) + shi + 1];
    }
    const int L1 = a1 - a0;
    const int ns = L1 + (b1r - b0r);

    float vsum = 0.0f;

    if (ns > 0) {
        // Adaptive border: grow while region has <64 candidates (cap bw=3, cap CAND_MAX)
        int ry0 = 0, ry1 = 0, cx0 = 0, cx1 = 0, tot = 0;
        for (int trial = 1; trial <= 3; trial++) {
            int ty0 = max(Sy * 2 - trial, 0),     ty1 = min(Sy * 2 + 1 + trial, GRID - 1);
            int tx0 = max(scx0 - trial, 0),       tx1 = min(scx1 + trial, GRID - 1);
            int t = 0;
            for (int ry = ty0; ry <= ty1; ry++) {
                int slo = (ry & 1) ? (GRID - 1 - tx1) : tx0;
                int shi = (ry & 1) ? (GRID - 1 - tx0) : tx1;
                t += cstT[(ry << 5) + shi + 1] - cstT[(ry << 5) + slo];
            }
            if (trial == 1 || t <= CAND_MAX) {
                ry0 = ty0; ry1 = ty1; cx0 = tx0; cx1 = tx1; tot = t;
            }
            if (t >= 64 || t > CAND_MAX) break;
        }
        (void)tot;

        // Stage region rows (snake-contiguous) into smem
        int off = 0;
        for (int ry = ry0; ry <= ry1; ry++) {
            int slo = (ry & 1) ? (GRID - 1 - cx1) : cx0;
            int shi = (ry & 1) ? (GRID - 1 - cx0) : cx1;
            int g0 = cstT[(ry << 5) + slo], g1 = cstT[(ry << 5) + shi + 1];
            int len = g1 - g0;
            if (off + len > CAND_MAX) len = CAND_MAX - off;   // statically unreachable guard
            for (int j = tid; j < len; j += S_THREADS)
                cand[off + j] = tgtg[g0 + j];
            off += len;
        }
        const int ncand = off;
        __syncthreads();

        // Geometric region bounds (INF margin at grid-clamped sides)
        const float rxl = (cx0 == 0)        ? -1e30f : XMIN + cx0 * CELLW;
        const float rxr = (cx1 == GRID - 1) ?  1e30f : XMIN + (cx1 + 1) * CELLW;
        const float ryl = (ry0 == 0)        ? -1e30f : XMIN + ry0 * CELLW;
        const float ryr = (ry1 == GRID - 1) ?  1e30f : XMIN + (ry1 + 1) * CELLW;

        const int nchunk = (ns + S_THREADS - 1) / S_THREADS;
        for (int ck = 0; ck < nchunk; ck++) {
            const int  i0    = ck * S_THREADS + tid;
            const bool valid = i0 < ns;
            const int  ii    = valid ? i0 : 0;
            const int  idx   = (ii < L1) ? (a0 + ii) : (b0r + (ii - L1));
            const float4 p = __ldg(&g_sorted[cs][idx]);
            const float mx = -2.0f * p.x, my = -2.0f * p.y, mz = -2.0f * p.z;
            float bestA = INFINITY, bestB = INFINITY;

            int j = 0;
            for (; j + 1 < ncand; j += 2) {            // broadcast LDS, 2-way ILP
                float4 t0 = cand[j];
                float4 t1 = cand[j + 1];
                bestA = fminf(bestA, fmaf(mx, t0.x, fmaf(my, t0.y, fmaf(mz, t0.z, t0.w))));
                bestB = fminf(bestB, fmaf(mx, t1.x, fmaf(my, t1.y, fmaf(mz, t1.z, t1.w))));
            }
            if (j < ncand) {
                float4 t0 = cand[j];
                bestA = fminf(bestA, fmaf(mx, t0.x, fmaf(my, t0.y, fmaf(mz, t0.z, t0.w))));
            }
            float best = fminf(bestA, bestB);
            float d = sqrtf(fmaxf(best + p.w, 0.0f));

            const float margin = fminf(fminf(p.x - rxl, rxr - p.x),
                                       fminf(p.y - ryl, ryr - p.y));
            const bool needy = valid && (d >= margin * 0.9999f);

            if (__ballot_sync(0xFFFFFFFFu, needy)) {
                // Warp-union window over needy lanes only
                const float dc = d * 1.0001f + 1e-6f;
                int fx0 = needy ? clampg((int)floorf((p.x - dc - XMIN) * INV_CELLW)) : GRID;
                int fx1 = needy ? clampg((int)floorf((p.x + dc - XMIN) * INV_CELLW)) : -1;
                int fy0 = needy ? clampg((int)floorf((p.y - dc - XMIN) * INV_CELLW)) : GRID;
                int fy1 = needy ? clampg((int)floorf((p.y + dc - XMIN) * INV_CELLW)) : -1;
                #pragma unroll
                for (int o = 16; o > 0; o >>= 1) {
                    fx0 = min(fx0, __shfl_xor_sync(0xFFFFFFFFu, fx0, o));
                    fx1 = max(fx1, __shfl_xor_sync(0xFFFFFFFFu, fx1, o));
                    fy0 = min(fy0, __shfl_xor_sync(0xFFFFFFFFu, fy0, o));
                    fy1 = max(fy1, __shfl_xor_sync(0xFFFFFFFFu, fy1, o));
                }
                for (int ry = fy0; ry <= fy1; ry++) {
                    int slo = (ry & 1) ? (GRID - 1 - fx1) : fx0;
                    int shi = (ry & 1) ? (GRID - 1 - fx0) : fx1;
                    int g0 = cstT[(ry << 5) + slo], g1 = cstT[(ry << 5) + shi + 1];
                    int jj = g0;
                    for (; jj + 1 < g1; jj += 2) {     // broadcast LDG (sparse regions)
                        float4 t0 = __ldg(&tgtg[jj]);
                        float4 t1 = __ldg(&tgtg[jj + 1]);
                        bestA = fminf(bestA, fmaf(mx, t0.x, fmaf(my, t0.y, fmaf(mz, t0.z, t0.w))));
                        bestB = fminf(bestB, fmaf(mx, t1.x, fmaf(my, t1.y, fmaf(mz, t1.z, t1.w))));
                    }
                    if (jj < g1) {
                        float4 t0 = __ldg(&tgtg[jj]);
                        bestA = fminf(bestA, fmaf(mx, t0.x, fmaf(my, t0.y, fmaf(mz, t0.z, t0.w))));
                    }
                }
                best = fminf(bestA, bestB);
                d = sqrtf(fmaxf(best + p.w, 0.0f));
            }

            vsum += valid ? d : 0.0f;
        }
    }

    // Block reduction (all blocks, even empty ones: vsum = 0)
    #pragma unroll
    for (int o = 16; o > 0; o >>= 1)
        vsum += __shfl_xor_sync(0xFFFFFFFFu, vsum, o);
    if (lane == 0) warpsums[wid] = vsum;
    __syncthreads();
    if (tid == 0) {
        float v = warpsums[0] + warpsums[1] + warpsums[2] + warpsums[3];
        if (v != 0.0f)
            atomicAdd(&g_sum, (double)v / ((double)BATCH * (double)NPTS));
    }

    // Ticket: last block publishes + resets
    __threadfence();
    if (tid == 0) s_done = atomicAdd(&g_tick, 1u);
    __syncthreads();
    if (s_done == NBLOCKS - 1 && tid == 0) {
        double total = atomicAdd(&g_sum, 0.0);   // atomic read
        out[0] = (float)total;
        g_sum  = 0.0;
        g_tick = 0;
    }
}

extern "C" void kernel_launch(void* const* d_in, const int* in_sizes, int n_in,
                              void* d_out, int out_size) {
    const float* pred = (const float*)d_in[0];
    const float* targ = (const float*)d_in[1];
    float* out = (float*)d_out;

    sort_kernel<<<NCLOUD, 512>>>(pred, targ);
    search_kernel<<<NBLOCKS, S_THREADS>>>(out);
}

// round 15
// speedup vs baseline: 2.5727x; 2.5727x over previous
#include <cuda_runtime.h>
#include <math.h>

// ChamferLoss: B=8, N=M=4096, D=3 — Morton-grid sort + warp-uniform per-cell pruned NN.

#define BATCH    8
#define NPTS     4096
#define NCLOUD   16
#define GRID     32
#define NCELL    (GRID * GRID)          // 1024
#define XMIN     (-3.2f)
#define CELLW    0.2f
#define INV_CELLW 5.0f
#define THREADS  256
#define SLICES   16
#define NCOMBO   16
#define NBLOCKS  (NCOMBO * SLICES)      // 256
#define NWARPS   (THREADS / 32)

__device__ float4 g_sorted[NCLOUD][NPTS];        // (x,y,z,|p|^2), Morton-cell-sorted
__device__ int    g_cellstart[NCLOUD][NCELL + 1];
__device__ double g_sum  = 0.0;
__device__ unsigned int g_tick = 0;

static __device__ __forceinline__ int clampg(int v) { return min(max(v, 0), GRID - 1); }
static __device__ __forceinline__ unsigned int part1by1(unsigned int x) {
    x &= 0x0000FFFFu;
    x = (x | (x << 8)) & 0x00FF00FFu;
    x = (x | (x << 4)) & 0x0F0F0F0Fu;
    x = (x | (x << 2)) & 0x33333333u;
    x = (x | (x << 1)) & 0x55555555u;
    return x;
}
static __device__ __forceinline__ int morton(int cx, int cy) {
    return (int)(part1by1((unsigned)cx) | (part1by1((unsigned)cy) << 1));
}
static __device__ __forceinline__ int cell_of(float x, float y) {
    return morton(clampg((int)((x - XMIN) * INV_CELLW)),
                  clampg((int)((y - XMIN) * INV_CELLW)));
}

// ---------------- Kernel 1: Morton-cell counting sort, one block per cloud ----------------
__global__ __launch_bounds__(512) void sort_kernel(
    const float* __restrict__ pred,
    const float* __restrict__ targ)
{
    __shared__ int cnt[NCELL];
    __shared__ int ofs[NCELL];
    __shared__ int wtot[16];

    const int c = blockIdx.x;
    const int b = c >> 1;
    const float* __restrict__ src = ((c & 1) ? targ : pred) + (size_t)b * NPTS * 3;
    const int tid = threadIdx.x;

    for (int k = tid; k < NCELL; k += 512) cnt[k] = 0;
    __syncthreads();
    #pragma unroll
    for (int i = tid; i < NPTS; i += 512)
        atomicAdd(&cnt[cell_of(src[3 * i], src[3 * i + 1])], 1);
    __syncthreads();

    {   // exclusive prefix over 1024 cells
        const int base = tid * 2;
        int c0 = cnt[base], c1 = cnt[base + 1];
        int tot = c0 + c1;
        int inc = tot;
        #pragma unroll
        for (int o = 1; o < 32; o <<= 1) {
            int n = __shfl_up_sync(0xFFFFFFFFu, inc, o);
            if ((tid & 31) >= o) inc += n;
        }
        if ((tid & 31) == 31) wtot[tid >> 5] = inc;
        __syncthreads();
        if (tid == 0) {
            int r = 0;
            #pragma unroll
            for (int w = 0; w < 16; w++) { int t = wtot[w]; wtot[w] = r; r += t; }
        }
        __syncthreads();
        int off = (inc - tot) + wtot[tid >> 5];
        ofs[base] = off;            ofs[base + 1] = off + c0;
        g_cellstart[c][base] = off; g_cellstart[c][base + 1] = off + c0;
        if (tid == 511) g_cellstart[c][NCELL] = off + tot;
    }
    __syncthreads();

    #pragma unroll
    for (int i = tid; i < NPTS; i += 512) {
        float x = src[3 * i], y = src[3 * i + 1], z = src[3 * i + 2];
        float w = fmaf(x, x, fmaf(y, y, z * z));
        int pos = atomicAdd(&ofs[cell_of(x, y)], 1);
        g_sorted[c][pos] = make_float4(x, y, z, w);
    }
}

// ---------------- Kernel 2: staged cloud + warp-uniform Morton-cell NN ----------------
struct Smem {
    float4 tgt[NPTS];            // 64 KB
    int    cst[NCELL + 1];       // 4.1 KB
    float  warpsums[NWARPS];
    unsigned int s_done;
};

__global__ __launch_bounds__(THREADS) void search_kernel(float* __restrict__ out)
{
    extern __shared__ char smem_raw[];
    Smem* s = (Smem*)smem_raw;
    const int tid = threadIdx.x;

    const int combo = blockIdx.x / SLICES;
    const int slice = blockIdx.x % SLICES;
    const int b     = combo >> 1;
    const int dir   = combo & 1;
    const int cs    = b * 2 + dir;
    const int ct    = b * 2 + (dir ^ 1);

    // Stage sorted target cloud + Morton cell prefix (coalesced)
    {
        const float4* __restrict__ g = g_sorted[ct];
        #pragma unroll
        for (int k = 0; k < NPTS / THREADS; k++)
            s->tgt[k * THREADS + tid] = g[k * THREADS + tid];
        for (int k = tid; k < NCELL + 1; k += THREADS)
            s->cst[k] = g_cellstart[ct][k];
    }

    // Source: Morton-sorted -> warp lanes are a compact quad
    const float4 p = g_sorted[cs][slice * THREADS + tid];
    const float mx = -2.0f * p.x, my = -2.0f * p.y, mz = -2.0f * p.z;

    __syncthreads();

    float bA = INFINITY, bB = INFINITY, bC = INFINITY, bD = INFINITY;

    auto scan_cell = [&](int cx, int cy) {
        const int m  = morton(cx, cy);
        const int j1 = s->cst[m + 1];
        int j = s->cst[m];
        for (; j + 3 < j1; j += 4) {          // broadcast LDS, 4-way MLP
            float4 t0 = s->tgt[j];
            float4 t1 = s->tgt[j + 1];
            float4 t2 = s->tgt[j + 2];
            float4 t3 = s->tgt[j + 3];
            bA = fminf(bA, fmaf(mx, t0.x, fmaf(my, t0.y, fmaf(mz, t0.z, t0.w))));
            bB = fminf(bB, fmaf(mx, t1.x, fmaf(my, t1.y, fmaf(mz, t1.z, t1.w))));
            bC = fminf(bC, fmaf(mx, t2.x, fmaf(my, t2.y, fmaf(mz, t2.z, t2.w))));
            bD = fminf(bD, fmaf(mx, t3.x, fmaf(my, t3.y, fmaf(mz, t3.z, t3.w))));
        }
        for (; j < j1; j++) {
            float4 t0 = s->tgt[j];
            bA = fminf(bA, fmaf(mx, t0.x, fmaf(my, t0.y, fmaf(mz, t0.z, t0.w))));
        }
    };
    auto scan_rect = [&](int ax0, int ax1, int ay0, int ay1) {
        for (int cy = ay0; cy <= ay1; cy++)
            for (int cx = ax0; cx <= ax1; cx++)
                scan_cell(cx, cy);
    };

    // Warp bbox in cell space
    int pcx = clampg((int)((p.x - XMIN) * INV_CELLW));
    int pcy = clampg((int)((p.y - XMIN) * INV_CELLW));
    int bx0 = pcx, bx1 = pcx, by0 = pcy, by1 = pcy;
    #pragma unroll
    for (int o = 16; o > 0; o >>= 1) {
        bx0 = min(bx0, __shfl_xor_sync(0xFFFFFFFFu, bx0, o));
        bx1 = max(bx1, __shfl_xor_sync(0xFFFFFFFFu, bx1, o));
        by0 = min(by0, __shfl_xor_sync(0xFFFFFFFFu, by0, o));
        by1 = max(by1, __shfl_xor_sync(0xFFFFFFFFu, by1, o));
    }

    // Phase A: bbox + 1 ring; expand perimeter while empty (warp-uniform)
    int wx0 = max(bx0 - 1, 0), wx1 = min(bx1 + 1, GRID - 1);
    int wy0 = max(by0 - 1, 0), wy1 = min(by1 + 1, GRID - 1);
    scan_rect(wx0, wx1, wy0, wy1);
    while (fminf(fminf(bA, bB), fminf(bC, bD)) == INFINITY &&
           !(wx0 == 0 && wx1 == GRID - 1 && wy0 == 0 && wy1 == GRID - 1)) {
        int nx0 = max(wx0 - 1, 0), nx1 = min(wx1 + 1, GRID - 1);
        int ny0 = max(wy0 - 1, 0), ny1 = min(wy1 + 1, GRID - 1);
        if (ny0 < wy0) scan_rect(nx0, nx1, ny0, ny0);
        if (ny1 > wy1) scan_rect(nx0, nx1, ny1, ny1);
        if (nx0 < wx0) scan_rect(nx0, nx0, wy0, wy1);
        if (nx1 > wx1) scan_rect(nx1, nx1, wy0, wy1);
        wx0 = nx0; wx1 = nx1; wy0 = ny0; wy1 = ny1;
    }
    float best = fminf(fminf(bA, bB), fminf(bC, bD));
    float d = sqrtf(fmaxf(best + p.w, 0.0f));

    // Phase B: per-lane margin; ballot-gated warp-union rescan (idempotent)
    float mgl = (wx0 == 0)        ? 1e30f : p.x - (XMIN + wx0 * CELLW);
    float mgr = (wx1 == GRID - 1) ? 1e30f : (XMIN + (wx1 + 1) * CELLW) - p.x;
    float mgb = (wy0 == 0)        ? 1e30f : p.y - (XMIN + wy0 * CELLW);
    float mgt = (wy1 == GRID - 1) ? 1e30f : (XMIN + (wy1 + 1) * CELLW) - p.y;
    float margin = fminf(fminf(mgl, mgr), fminf(mgb, mgt));
    const bool needy = (d >= margin * 0.9999f);

    if (__ballot_sync(0xFFFFFFFFu, needy)) {
        float dc = d * 1.0001f + 1e-6f;
        int fx0 = needy ? clampg((int)floorf((p.x - dc - XMIN) * INV_CELLW)) : GRID;
        int fx1 = needy ? clampg((int)floorf((p.x + dc - XMIN) * INV_CELLW)) : -1;
        int fy0 = needy ? clampg((int)floorf((p.y - dc - XMIN) * INV_CELLW)) : GRID;
        int fy1 = needy ? clampg((int)floorf((p.y + dc - XMIN) * INV_CELLW)) : -1;
        #pragma unroll
        for (int o = 16; o > 0; o >>= 1) {
            fx0 = min(fx0, __shfl_xor_sync(0xFFFFFFFFu, fx0, o));
            fx1 = max(fx1, __shfl_xor_sync(0xFFFFFFFFu, fx1, o));
            fy0 = min(fy0, __shfl_xor_sync(0xFFFFFFFFu, fy0, o));
            fy1 = max(fy1, __shfl_xor_sync(0xFFFFFFFFu, fy1, o));
        }
        // Scan only the delta around the already-scanned rectangle
        fx0 = min(fx0, wx0); fx1 = max(fx1, wx1);
        fy0 = min(fy0, wy0); fy1 = max(fy1, wy1);
        for (int ry = fy0; ry <= fy1; ry++) {
            if (ry < wy0 || ry > wy1) {
                scan_rect(fx0, fx1, ry, ry);
            } else {
                if (fx0 < wx0) scan_rect(fx0, wx0 - 1, ry, ry);
                if (fx1 > wx1) scan_rect(wx1 + 1, fx1, ry, ry);
            }
        }
        best = fminf(fminf(bA, bB), fminf(bC, bD));
        d = sqrtf(fmaxf(best + p.w, 0.0f));
    }

    // Reduction
    float acc = d;
    #pragma unroll
    for (int o = 16; o > 0; o >>= 1)
        acc += __shfl_xor_sync(0xFFFFFFFFu, acc, o);
    const int lane = tid & 31, wid = tid >> 5;
    if (lane == 0) s->warpsums[wid] = acc;
    __syncthreads();
    if (tid == 0) {
        float v = 0.0f;
        #pragma unroll
        for (int k = 0; k < NWARPS; k++) v += s->warpsums[k];
        atomicAdd(&g_sum, (double)v / ((double)BATCH * (double)NPTS));
    }

    // Ticket: last block publishes + resets
    __threadfence();
    if (tid == 0) s->s_done = atomicAdd(&g_tick, 1u);
    __syncthreads();
    if (s->s_done == NBLOCKS - 1 && tid == 0) {
        double total = atomicAdd(&g_sum, 0.0);   // atomic read
        out[0] = (float)total;
        g_sum  = 0.0;
        g_tick = 0;
    }
}

extern "C" void kernel_launch(void* const* d_in, const int* in_sizes, int n_in,
                              void* d_out, int out_size) {
    const float* pred = (const float*)d_in[0];
    const float* targ = (const float*)d_in[1];
    float* out = (float*)d_out;

    static bool attr_set = false;
    if (!attr_set) {
        cudaFuncSetAttribute(search_kernel,
                             cudaFuncAttributeMaxDynamicSharedMemorySize,
                             (int)sizeof(Smem));
        attr_set = true;
    }
    sort_kernel<<<NCLOUD, 512>>>(pred, targ);
    search_kernel<<<NBLOCKS, THREADS, sizeof(Smem)>>>(out);
}

// round 16
// speedup vs baseline: 7.7909x; 3.0282x over previous
#include <cuda_runtime.h>
#include <math.h>

// ChamferLoss: B=8, N=M=4096, D=3 — dual-order sort (Morton sources, row-major targets)
// + smem-staged warp-uniform pruned NN.

#define BATCH    8
#define NPTS     4096
#define NCLOUD   16
#define GRID     32
#define NCELL    (GRID * GRID)          // 1024
#define XMIN     (-3.2f)
#define CELLW    0.2f
#define INV_CELLW 5.0f
#define THREADS  256
#define SLICES   16
#define NCOMBO   16
#define NBLOCKS  (NCOMBO * SLICES)      // 256
#define NWARPS   (THREADS / 32)

__device__ float4 g_src[NCLOUD][NPTS];           // Morton-cell-sorted (x,y,z,|p|^2)
__device__ float4 g_tgt[NCLOUD][NPTS];           // row-major-cell-sorted
__device__ int    g_rowstart[NCLOUD][NCELL + 1]; // prefix for row-major order
__device__ double g_sum  = 0.0;
__device__ unsigned int g_tick = 0;

static __device__ __forceinline__ int clampg(int v) { return min(max(v, 0), GRID - 1); }
static __device__ __forceinline__ unsigned int part1by1(unsigned int x) {
    x &= 0x0000FFFFu;
    x = (x | (x << 8)) & 0x00FF00FFu;
    x = (x | (x << 4)) & 0x0F0F0F0Fu;
    x = (x | (x << 2)) & 0x33333333u;
    x = (x | (x << 1)) & 0x55555555u;
    return x;
}

// ---------------- Kernel 1: dual counting sort per cloud ----------------
__global__ __launch_bounds__(512) void sort_kernel(
    const float* __restrict__ pred,
    const float* __restrict__ targ)
{
    __shared__ int cntR[NCELL], ofsR[NCELL];
    __shared__ int cntM[NCELL], ofsM[NCELL];
    __shared__ int wtot[16];

    const int c = blockIdx.x;
    const int b = c >> 1;
    const float* __restrict__ src = ((c & 1) ? targ : pred) + (size_t)b * NPTS * 3;
    const int tid = threadIdx.x;

    for (int k = tid; k < NCELL; k += 512) { cntR[k] = 0; cntM[k] = 0; }
    __syncthreads();
    #pragma unroll
    for (int i = tid; i < NPTS; i += 512) {
        int cx = clampg((int)((src[3 * i] - XMIN) * INV_CELLW));
        int cy = clampg((int)((src[3 * i + 1] - XMIN) * INV_CELLW));
        atomicAdd(&cntR[(cy << 5) | cx], 1);
        atomicAdd(&cntM[part1by1(cx) | (part1by1(cy) << 1)], 1);
    }
    __syncthreads();

    // Exclusive prefix of cntR -> ofsR (+ g_rowstart), then cntM -> ofsM
    #pragma unroll
    for (int pass = 0; pass < 2; pass++) {
        const int* cnt = pass ? cntM : cntR;
        int* ofs = pass ? ofsM : ofsR;
        const int base = tid * 2;
        int c0 = cnt[base], c1 = cnt[base + 1];
        int tot = c0 + c1;
        int inc = tot;
        #pragma unroll
        for (int o = 1; o < 32; o <<= 1) {
            int n = __shfl_up_sync(0xFFFFFFFFu, inc, o);
            if ((tid & 31) >= o) inc += n;
        }
        if ((tid & 31) == 31) wtot[tid >> 5] = inc;
        __syncthreads();
        if (tid == 0) {
            int r = 0;
            #pragma unroll
            for (int w = 0; w < 16; w++) { int t = wtot[w]; wtot[w] = r; r += t; }
        }
        __syncthreads();
        int off = (inc - tot) + wtot[tid >> 5];
        ofs[base] = off; ofs[base + 1] = off + c0;
        if (!pass) {
            g_rowstart[c][base] = off; g_rowstart[c][base + 1] = off + c0;
            if (tid == 511) g_rowstart[c][NCELL] = off + tot;
        }
        __syncthreads();
    }

    #pragma unroll
    for (int i = tid; i < NPTS; i += 512) {
        float x = src[3 * i], y = src[3 * i + 1], z = src[3 * i + 2];
        float w = fmaf(x, x, fmaf(y, y, z * z));
        int cx = clampg((int)((x - XMIN) * INV_CELLW));
        int cy = clampg((int)((y - XMIN) * INV_CELLW));
        float4 v = make_float4(x, y, z, w);
        int pr = atomicAdd(&ofsR[(cy << 5) | cx], 1);
        g_tgt[c][pr] = v;
        int pm = atomicAdd(&ofsM[part1by1(cx) | (part1by1(cy) << 1)], 1);
        g_src[c][pm] = v;
    }
}

// ---------------- Kernel 2: staged row-major cloud + Morton sources ----------------
struct Smem {
    float4 tgt[NPTS];            // 64 KB
    int    cst[NCELL + 1];       // 4.1 KB
    float  warpsums[NWARPS];
    unsigned int s_done;
};

__global__ __launch_bounds__(THREADS) void search_kernel(float* __restrict__ out)
{
    extern __shared__ char smem_raw[];
    Smem* s = (Smem*)smem_raw;
    const int tid = threadIdx.x;

    const int combo = blockIdx.x / SLICES;
    const int slice = blockIdx.x % SLICES;
    const int b     = combo >> 1;
    const int dir   = combo & 1;
    const int cs    = b * 2 + dir;
    const int ct    = b * 2 + (dir ^ 1);

    // Stage row-major target cloud + prefix (coalesced)
    {
        const float4* __restrict__ g = g_tgt[ct];
        #pragma unroll
        for (int k = 0; k < NPTS / THREADS; k++)
            s->tgt[k * THREADS + tid] = g[k * THREADS + tid];
        for (int k = tid; k < NCELL + 1; k += THREADS)
            s->cst[k] = g_rowstart[ct][k];
    }

    // Source: Morton-sorted -> warp lanes form a compact quad
    const float4 p = g_src[cs][slice * THREADS + tid];
    const float mx = -2.0f * p.x, my = -2.0f * p.y, mz = -2.0f * p.z;

    __syncthreads();

    float bA = INFINITY, bB = INFINITY, bC = INFINITY, bD = INFINITY;

    // One contiguous segment per grid row (row-major target order)
    auto scan_rows = [&](int ax0, int ax1, int ay0, int ay1) {
        for (int ry = ay0; ry <= ay1; ry++) {
            const int j1 = s->cst[(ry << 5) + ax1 + 1];
            int j = s->cst[(ry << 5) + ax0];
            for (; j + 3 < j1; j += 4) {          // broadcast LDS, 4-way MLP
                float4 t0 = s->tgt[j];
                float4 t1 = s->tgt[j + 1];
                float4 t2 = s->tgt[j + 2];
                float4 t3 = s->tgt[j + 3];
                bA = fminf(bA, fmaf(mx, t0.x, fmaf(my, t0.y, fmaf(mz, t0.z, t0.w))));
                bB = fminf(bB, fmaf(mx, t1.x, fmaf(my, t1.y, fmaf(mz, t1.z, t1.w))));
                bC = fminf(bC, fmaf(mx, t2.x, fmaf(my, t2.y, fmaf(mz, t2.z, t2.w))));
                bD = fminf(bD, fmaf(mx, t3.x, fmaf(my, t3.y, fmaf(mz, t3.z, t3.w))));
            }
            for (; j < j1; j++) {
                float4 t0 = s->tgt[j];
                bA = fminf(bA, fmaf(mx, t0.x, fmaf(my, t0.y, fmaf(mz, t0.z, t0.w))));
            }
        }
    };

    // Warp bbox in cell space
    int pcx = clampg((int)((p.x - XMIN) * INV_CELLW));
    int pcy = clampg((int)((p.y - XMIN) * INV_CELLW));
    int bx0 = pcx, bx1 = pcx, by0 = pcy, by1 = pcy;
    #pragma unroll
    for (int o = 16; o > 0; o >>= 1) {
        bx0 = min(bx0, __shfl_xor_sync(0xFFFFFFFFu, bx0, o));
        bx1 = max(bx1, __shfl_xor_sync(0xFFFFFFFFu, bx1, o));
        by0 = min(by0, __shfl_xor_sync(0xFFFFFFFFu, by0, o));
        by1 = max(by1, __shfl_xor_sync(0xFFFFFFFFu, by1, o));
    }

    // Phase A: bbox + 1 ring; expand perimeter while empty (warp-uniform)
    int wx0 = max(bx0 - 1, 0), wx1 = min(bx1 + 1, GRID - 1);
    int wy0 = max(by0 - 1, 0), wy1 = min(by1 + 1, GRID - 1);
    scan_rows(wx0, wx1, wy0, wy1);
    while (fminf(fminf(bA, bB), fminf(bC, bD)) == INFINITY &&
           !(wx0 == 0 && wx1 == GRID - 1 && wy0 == 0 && wy1 == GRID - 1)) {
        int nx0 = max(wx0 - 1, 0), nx1 = min(wx1 + 1, GRID - 1);
        int ny0 = max(wy0 - 1, 0), ny1 = min(wy1 + 1, GRID - 1);
        if (ny0 < wy0) scan_rows(nx0, nx1, ny0, ny0);
        if (ny1 > wy1) scan_rows(nx0, nx1, ny1, ny1);
        if (nx0 < wx0) scan_rows(nx0, nx0, wy0, wy1);
        if (nx1 > wx1) scan_rows(nx1, nx1, wy0, wy1);
        wx0 = nx0; wx1 = nx1; wy0 = ny0; wy1 = ny1;
    }
    float best = fminf(fminf(bA, bB), fminf(bC, bD));
    float d = sqrtf(fmaxf(best + p.w, 0.0f));

    // Phase B: per-lane margin; ballot-gated warp-union delta rescan
    float mgl = (wx0 == 0)        ? 1e30f : p.x - (XMIN + wx0 * CELLW);
    float mgr = (wx1 == GRID - 1) ? 1e30f : (XMIN + (wx1 + 1) * CELLW) - p.x;
    float mgb = (wy0 == 0)        ? 1e30f : p.y - (XMIN + wy0 * CELLW);
    float mgt = (wy1 == GRID - 1) ? 1e30f : (XMIN + (wy1 + 1) * CELLW) - p.y;
    float margin = fminf(fminf(mgl, mgr), fminf(mgb, mgt));
    const bool needy = (d >= margin * 0.9999f);

    if (__ballot_sync(0xFFFFFFFFu, needy)) {
        float dc = d * 1.0001f + 1e-6f;
        int fx0 = needy ? clampg((int)floorf((p.x - dc - XMIN) * INV_CELLW)) : GRID;
        int fx1 = needy ? clampg((int)floorf((p.x + dc - XMIN) * INV_CELLW)) : -1;
        int fy0 = needy ? clampg((int)floorf((p.y - dc - XMIN) * INV_CELLW)) : GRID;
        int fy1 = needy ? clampg((int)floorf((p.y + dc - XMIN) * INV_CELLW)) : -1;
        #pragma unroll
        for (int o = 16; o > 0; o >>= 1) {
            fx0 = min(fx0, __shfl_xor_sync(0xFFFFFFFFu, fx0, o));
            fx1 = max(fx1, __shfl_xor_sync(0xFFFFFFFFu, fx1, o));
            fy0 = min(fy0, __shfl_xor_sync(0xFFFFFFFFu, fy0, o));
            fy1 = max(fy1, __shfl_xor_sync(0xFFFFFFFFu, fy1, o));
        }
        fx0 = min(fx0, wx0); fx1 = max(fx1, wx1);
        fy0 = min(fy0, wy0); fy1 = max(fy1, wy1);
        for (int ry = fy0; ry <= fy1; ry++) {
            if (ry < wy0 || ry > wy1) {
                scan_rows(fx0, fx1, ry, ry);
            } else {
                if (fx0 < wx0) scan_rows(fx0, wx0 - 1, ry, ry);
                if (fx1 > wx1) scan_rows(wx1 + 1, fx1, ry, ry);
            }
        }
        best = fminf(fminf(bA, bB), fminf(bC, bD));
        d = sqrtf(fmaxf(best + p.w, 0.0f));
    }

    // Reduction
    float acc = d;
    #pragma unroll
    for (int o = 16; o > 0; o >>= 1)
        acc += __shfl_xor_sync(0xFFFFFFFFu, acc, o);
    const int lane = tid & 31, wid = tid >> 5;
    if (lane == 0) s->warpsums[wid] = acc;
    __syncthreads();
    if (tid == 0) {
        float v = 0.0f;
        #pragma unroll
        for (int k = 0; k < NWARPS; k++) v += s->warpsums[k];
        atomicAdd(&g_sum, (double)v / ((double)BATCH * (double)NPTS));
    }

    // Ticket: last block publishes + resets
    __threadfence();
    if (tid == 0) s->s_done = atomicAdd(&g_tick, 1u);
    __syncthreads();
    if (s->s_done == NBLOCKS - 1 && tid == 0) {
        double total = atomicAdd(&g_sum, 0.0);   // atomic read
        out[0] = (float)total;
        g_sum  = 0.0;
        g_tick = 0;
    }
}

extern "C" void kernel_launch(void* const* d_in, const int* in_sizes, int n_in,
                              void* d_out, int out_size) {
    const float* pred = (const float*)d_in[0];
    const float* targ = (const float*)d_in[1];
    float* out = (float*)d_out;

    static bool attr_set = false;
    if (!attr_set) {
        cudaFuncSetAttribute(search_kernel,
                             cudaFuncAttributeMaxDynamicSharedMemorySize,
                             (int)sizeof(Smem));
        attr_set = true;
    }
    sort_kernel<<<NCLOUD, 512>>>(pred, targ);
    search_kernel<<<NBLOCKS, THREADS, sizeof(Smem)>>>(out);
}